// round 3
// baseline (speedup 1.0000x reference)
#include <cuda_runtime.h>

// Hidden layer-2 activations (post-relu), produced by the w3 stage, consumed
// by the fused final stage (last block).
__device__ __align__(16) float g_h2[256];
// Last-block-done ticket. Self-resetting so every graph replay starts identically.
__device__ int g_ticket = 0;

#define RPB 2                       // w3 rows per block
#define NBLK (256 / RPB)            // 128 blocks = one wave

__device__ __forceinline__ float dot4(float4 a, float4 b) {
    return a.x * b.x + a.y * b.y + a.z * b.z + a.w * b.w;
}

__global__ void __launch_bounds__(256, 1)
actor_fused_kernel(const float* __restrict__ x,
                   const float* __restrict__ conv_w, const float* __restrict__ conv_b,
                   const float* __restrict__ w0, const float* __restrict__ b0,
                   const float* __restrict__ w1, const float* __restrict__ b1,
                   const float* __restrict__ w2, const float* __restrict__ b2,
                   const float* __restrict__ w3, const float* __restrict__ b3,
                   const float* __restrict__ w4, const float* __restrict__ b4,
                   float* __restrict__ out) {
    __shared__ __align__(16) float h[2048];
    __shared__ float red[RPB][8];
    __shared__ int is_last;

    const int tid  = threadIdx.x;
    const int row0 = blockIdx.x * RPB;

    // ================= Front-batched independent loads =================
    // Everything below has no inter-dependency: one memory latency covers all.

    // w3 slices for this block's 2 rows (4x LDG.128)
    const float4* wr0 = reinterpret_cast<const float4*>(w3 + (size_t)row0 * 2048);
    const float4* wr1 = reinterpret_cast<const float4*>(w3 + (size_t)(row0 + 1) * 2048);
    const float4 a0 = wr0[tid * 2], a1 = wr0[tid * 2 + 1];
    const float4 c0 = wr1[tid * 2], c1 = wr1[tid * 2 + 1];

    // conv weights for this thread's channel
    const int c = tid & 127;
    const float4 cw = *reinterpret_cast<const float4*>(conv_w + c * 4);
    const float  cb = conv_b[c];

    // x values (uniform-address scalar loads broadcast; float4 windows per half)
    const float x7 = x[7], x15 = x[15], x39 = x[39];
    const int lohw = (tid < 128);
    const float4 xA0 = *reinterpret_cast<const float4*>(x + (lohw ? 16 : 24));
    const float4 xA1 = *reinterpret_cast<const float4*>(x + (lohw ? 20 : 28));
    const float4 xB0 = *reinterpret_cast<const float4*>(x + 32);
    const float4 xB1 = *reinterpret_cast<const float4*>(x + 36);

    // scalar-affine branch params (used by tid<128 only; loaded by all, harmless)
    const float w0v = w0[c], b0v = b0[c];
    const float w1v = w1[c], b1v = b1[c];
    const float w2v = w2[c], b2v = b2[c];

    // bias for this block's h2 rows (used by tid<RPB)
    const float b3p = b3[row0 + (tid & 1)];

    // prefetch w4 slice + b4 for the fused final stage (used only by last block)
    const int pidx = (tid < 192) ? tid : 0;
    const float4* w44 = reinterpret_cast<const float4*>(w4);
    const float4 p4a = w44[pidx * 2], p4b = w44[pidx * 2 + 1];
    const float  b4p = b4[(tid >> 5) < 6 ? (tid >> 5) : 0];

    // ================= Build h[2048] in smem (registers only as inputs) ====
    // h[   0: 128) = relu(w0*x[0,7] + b0)
    // h[ 128: 256) = relu(w1*x[1,7] + b1)
    // h[ 256: 896) = relu(conv1d(x[2,0:8]))  channel-major [128,5]
    // h[ 896:1536) = relu(conv1d(x[3,0:8]))  channel-major [128,5]
    // h[1536:1920) = relu(conv1d(x[4,0:6]))  channel-major [128,3]
    // h[1920:2048) = w2*x[4,7] + b2          (NO relu)
    {
        float xw[8];
        xw[0] = xA0.x; xw[1] = xA0.y; xw[2] = xA0.z; xw[3] = xA0.w;
        xw[4] = xA1.x; xw[5] = xA1.y; xw[6] = xA1.z; xw[7] = xA1.w;

        if (lohw) {
            h[c]        = fmaxf(fmaf(w0v, x7,  b0v), 0.0f);
            h[128 + c]  = fmaxf(fmaf(w1v, x15, b1v), 0.0f);
            h[1920 + c] =       fmaf(w2v, x39, b2v);   // no relu
            #pragma unroll
            for (int t = 0; t < 5; t++) {
                float s = fmaf(cw.x, xw[t],
                          fmaf(cw.y, xw[t + 1],
                          fmaf(cw.z, xw[t + 2],
                          fmaf(cw.w, xw[t + 3], cb))));
                h[256 + c * 5 + t] = fmaxf(s, 0.0f);
            }
        } else {
            #pragma unroll
            for (int t = 0; t < 5; t++) {
                float s = fmaf(cw.x, xw[t],
                          fmaf(cw.y, xw[t + 1],
                          fmaf(cw.z, xw[t + 2],
                          fmaf(cw.w, xw[t + 3], cb))));
                h[896 + c * 5 + t] = fmaxf(s, 0.0f);
            }
            float xv[8];
            xv[0] = xB0.x; xv[1] = xB0.y; xv[2] = xB0.z; xv[3] = xB0.w;
            xv[4] = xB1.x; xv[5] = xB1.y; xv[6] = xB1.z; xv[7] = xB1.w;
            #pragma unroll
            for (int t = 0; t < 3; t++) {
                float s = fmaf(cw.x, xv[t],
                          fmaf(cw.y, xv[t + 1],
                          fmaf(cw.z, xv[t + 2],
                          fmaf(cw.w, xv[t + 3], cb))));
                h[1536 + c * 3 + t] = fmaxf(s, 0.0f);
            }
        }
    }
    __syncthreads();

    // ======== 2 rows of relu(w3 @ h + b3); w3 already in registers ========
    const float4* hv = reinterpret_cast<const float4*>(h);
    const float4 h0 = hv[tid * 2];
    const float4 h1 = hv[tid * 2 + 1];

    float p0 = dot4(a0, h0) + dot4(a1, h1);
    float p1 = dot4(c0, h0) + dot4(c1, h1);

    #pragma unroll
    for (int o = 16; o > 0; o >>= 1) {
        p0 += __shfl_down_sync(0xFFFFFFFFu, p0, o);
        p1 += __shfl_down_sync(0xFFFFFFFFu, p1, o);
    }
    if ((tid & 31) == 0) {
        red[0][tid >> 5] = p0;
        red[1][tid >> 5] = p1;
    }
    __syncthreads();
    if (tid < RPB) {
        float s = red[tid][0] + red[tid][1] + red[tid][2] + red[tid][3]
                + red[tid][4] + red[tid][5] + red[tid][6] + red[tid][7];
        g_h2[row0 + tid] = fmaxf(s + b3p, 0.0f);
    }

    // ================= Last-block-done: fused final 6x256 GEMV ============
    __threadfence();             // make g_h2 rows globally visible (L2)
    __syncthreads();             // all warps done (incl. g_h2 store)
    if (tid == 0) {
        is_last = (atomicAdd(&g_ticket, 1) == NBLK - 1);
    }
    __syncthreads();

    if (is_last) {
        if (tid < 192) {
            const int lane = tid & 31;
            const float4* gv = reinterpret_cast<const float4*>(g_h2);
            // __ldcg: read through L2 (bypass this SM's L1) — other blocks wrote it
            const float4 g0 = __ldcg(gv + lane * 2);
            const float4 g1 = __ldcg(gv + lane * 2 + 1);
            float p = dot4(p4a, g0) + dot4(p4b, g1);
            #pragma unroll
            for (int o = 16; o > 0; o >>= 1)
                p += __shfl_down_sync(0xFFFFFFFFu, p, o);
            if (lane == 0) out[tid >> 5] = p + b4p;
        }
        if (tid == 0) g_ticket = 0;   // reset for next graph replay
    }
}

extern "C" void kernel_launch(void* const* d_in, const int* in_sizes, int n_in,
                              void* d_out, int out_size) {
    const float* x      = (const float*)d_in[0];
    const float* conv_w = (const float*)d_in[1];
    const float* conv_b = (const float*)d_in[2];
    const float* w0 = (const float*)d_in[3];
    const float* b0 = (const float*)d_in[4];
    const float* w1 = (const float*)d_in[5];
    const float* b1 = (const float*)d_in[6];
    const float* w2 = (const float*)d_in[7];
    const float* b2 = (const float*)d_in[8];
    const float* w3 = (const float*)d_in[9];
    const float* b3 = (const float*)d_in[10];
    const float* w4 = (const float*)d_in[11];
    const float* b4 = (const float*)d_in[12];
    float* out = (float*)d_out;

    actor_fused_kernel<<<NBLK, 256>>>(x, conv_w, conv_b,
                                      w0, b0, w1, b1, w2, b2, w3, b3,
                                      w4, b4, out);
}

// round 5
// speedup vs baseline: 1.0294x; 1.0294x over previous
#include <cuda_runtime.h>

// Atomic partial-output accumulators, padded to one 128B L2 line each so the
// 6 counters serialize independently at the LTS atomic ALUs. Zero at module
// load; the last block of each launch resets them, so every graph replay
// starts from identical state.
__device__ float g_acc[6 * 32];
// Last-block-done ticket, self-resetting.
__device__ int g_ticket = 0;

#define RPB 2                       // w3 rows per block
#define NBLK (256 / RPB)            // 128 blocks = one wave

__device__ __forceinline__ float dot4(float4 a, float4 b) {
    return a.x * b.x + a.y * b.y + a.z * b.z + a.w * b.w;
}

__global__ void __launch_bounds__(256, 1)
actor_fused_kernel(const float* __restrict__ x,
                   const float* __restrict__ conv_w, const float* __restrict__ conv_b,
                   const float* __restrict__ w0, const float* __restrict__ b0,
                   const float* __restrict__ w1, const float* __restrict__ b1,
                   const float* __restrict__ w2, const float* __restrict__ b2,
                   const float* __restrict__ w3, const float* __restrict__ b3,
                   const float* __restrict__ w4, const float* __restrict__ b4,
                   float* __restrict__ out) {
    __shared__ __align__(16) float h[2048];
    __shared__ float red[RPB][8];

    const int tid  = threadIdx.x;
    const int lane = tid & 31;
    const int row0 = blockIdx.x * RPB;

    // ================= Front-batched independent loads =================
    // All issued back-to-back: one memory latency covers everything.

    // w3 slices for this block's 2 rows (4x LDG.128, coalesced per warp)
    const float4* wr0 = reinterpret_cast<const float4*>(w3 + (size_t)row0 * 2048);
    const float4* wr1 = reinterpret_cast<const float4*>(w3 + (size_t)(row0 + 1) * 2048);
    const float4 a0 = wr0[tid * 2], a1 = wr0[tid * 2 + 1];
    const float4 c0 = wr1[tid * 2], c1 = wr1[tid * 2 + 1];

    // conv weights for this thread's channel
    const int c = tid & 127;
    const float4 cw = *reinterpret_cast<const float4*>(conv_w + c * 4);
    const float  cb = conv_b[c];

    // x values (scalar broadcasts + per-half float4 windows)
    const float x7 = x[7], x15 = x[15], x39 = x[39];
    const int lohw = (tid < 128);
    const float4 xA0 = *reinterpret_cast<const float4*>(x + (lohw ? 16 : 24));
    const float4 xA1 = *reinterpret_cast<const float4*>(x + (lohw ? 20 : 28));
    const float4 xB0 = *reinterpret_cast<const float4*>(x + 32);
    const float4 xB1 = *reinterpret_cast<const float4*>(x + 36);

    // scalar-affine branch params
    const float w0v = w0[c], b0v = b0[c];
    const float w1v = w1[c], b1v = b1[c];
    const float w2v = w2[c], b2v = b2[c];

    // bias for this block's h2 rows (consumed by tid<12 in the tail)
    const float b3p = b3[row0 + (tid & 1)];

    // w4 column entries: thread t<12 handles (w = t>>1, r = row0 + (t&1))
    const int widx = (tid < 12) ? ((tid >> 1) * 256 + row0 + (tid & 1)) : row0;
    const float w4v = w4[widx];

    // b4 for the fused tail (warp-0 lanes 0..5 of whichever block is last)
    const float b4p = b4[lane < 6 ? lane : 0];

    // ================= Build h[2048] in smem =================
    // h[   0: 128) = relu(w0*x[0,7] + b0)
    // h[ 128: 256) = relu(w1*x[1,7] + b1)
    // h[ 256: 896) = relu(conv1d(x[2,0:8]))  channel-major [128,5]
    // h[ 896:1536) = relu(conv1d(x[3,0:8]))  channel-major [128,5]
    // h[1536:1920) = relu(conv1d(x[4,0:6]))  channel-major [128,3]
    // h[1920:2048) = w2*x[4,7] + b2          (NO relu)
    {
        float xw[8];
        xw[0] = xA0.x; xw[1] = xA0.y; xw[2] = xA0.z; xw[3] = xA0.w;
        xw[4] = xA1.x; xw[5] = xA1.y; xw[6] = xA1.z; xw[7] = xA1.w;

        if (lohw) {
            h[c]        = fmaxf(fmaf(w0v, x7,  b0v), 0.0f);
            h[128 + c]  = fmaxf(fmaf(w1v, x15, b1v), 0.0f);
            h[1920 + c] =       fmaf(w2v, x39, b2v);   // no relu
            #pragma unroll
            for (int t = 0; t < 5; t++) {
                float s = fmaf(cw.x, xw[t],
                          fmaf(cw.y, xw[t + 1],
                          fmaf(cw.z, xw[t + 2],
                          fmaf(cw.w, xw[t + 3], cb))));
                h[256 + c * 5 + t] = fmaxf(s, 0.0f);
            }
        } else {
            #pragma unroll
            for (int t = 0; t < 5; t++) {
                float s = fmaf(cw.x, xw[t],
                          fmaf(cw.y, xw[t + 1],
                          fmaf(cw.z, xw[t + 2],
                          fmaf(cw.w, xw[t + 3], cb))));
                h[896 + c * 5 + t] = fmaxf(s, 0.0f);
            }
            float xv[8];
            xv[0] = xB0.x; xv[1] = xB0.y; xv[2] = xB0.z; xv[3] = xB0.w;
            xv[4] = xB1.x; xv[5] = xB1.y; xv[6] = xB1.z; xv[7] = xB1.w;
            #pragma unroll
            for (int t = 0; t < 3; t++) {
                float s = fmaf(cw.x, xv[t],
                          fmaf(cw.y, xv[t + 1],
                          fmaf(cw.z, xv[t + 2],
                          fmaf(cw.w, xv[t + 3], cb))));
                h[1536 + c * 3 + t] = fmaxf(s, 0.0f);
            }
        }
    }
    __syncthreads();                               // BAR1: h ready

    // ======== 2 rows of (w3 @ h); w3 already in registers ========
    const float4* hv = reinterpret_cast<const float4*>(h);
    const float4 h0 = hv[tid * 2];
    const float4 h1 = hv[tid * 2 + 1];

    float p0 = dot4(a0, h0) + dot4(a1, h1);
    float p1 = dot4(c0, h0) + dot4(c1, h1);

    #pragma unroll
    for (int o = 16; o > 0; o >>= 1) {
        p0 += __shfl_down_sync(0xFFFFFFFFu, p0, o);
        p1 += __shfl_down_sync(0xFFFFFFFFu, p1, o);
    }
    if (lane == 0) {
        red[0][tid >> 5] = p0;
        red[1][tid >> 5] = p1;
    }
    __syncthreads();                               // BAR2: red ready (warps 1..7 done after this)

    // ======== Warp 0 only: partial outputs + ticket + fused tail ========
    if (tid < 32) {
        // threads 0..11: g_acc[w] += w4[w][row0+r] * relu(h2[row0+r] )
        if (tid < 12) {
            const int r = tid & 1;
            float s = red[r][0] + red[r][1] + red[r][2] + red[r][3]
                    + red[r][4] + red[r][5] + red[r][6] + red[r][7];
            s = fmaxf(s + b3p, 0.0f);              // b3p = b3[row0 + (tid&1)]
            atomicAdd(&g_acc[(tid >> 1) * 32], s * w4v);
        }
        __syncwarp();                              // REDs happen-before tid0's fence
        int t = 0;
        if (lane == 0) {
            __threadfence();                       // release warp-0 REDs to device scope
            t = atomicAdd(&g_ticket, 1);
        }
        t = __shfl_sync(0xFFFFFFFFu, t, 0);
        if (t == NBLK - 1) {
            __threadfence();                       // acquire: all blocks' REDs visible
            if (lane < 6) {
                float acc = __ldcg(&g_acc[lane * 32]);
                out[lane] = acc + b4p;
                g_acc[lane * 32] = 0.0f;           // reset for next replay
            }
            if (lane == 0) g_ticket = 0;
        }
    }
}

extern "C" void kernel_launch(void* const* d_in, const int* in_sizes, int n_in,
                              void* d_out, int out_size) {
    const float* x      = (const float*)d_in[0];
    const float* conv_w = (const float*)d_in[1];
    const float* conv_b = (const float*)d_in[2];
    const float* w0 = (const float*)d_in[3];
    const float* b0 = (const float*)d_in[4];
    const float* w1 = (const float*)d_in[5];
    const float* b1 = (const float*)d_in[6];
    const float* w2 = (const float*)d_in[7];
    const float* b2 = (const float*)d_in[8];
    const float* w3 = (const float*)d_in[9];
    const float* b3 = (const float*)d_in[10];
    const float* w4 = (const float*)d_in[11];
    const float* b4 = (const float*)d_in[12];
    float* out = (float*)d_out;

    actor_fused_kernel<<<NBLK, 256>>>(x, conv_w, conv_b,
                                      w0, b0, w1, b1, w2, b2, w3, b3,
                                      w4, b4, out);
}